// round 4
// baseline (speedup 1.0000x reference)
#include <cuda_runtime.h>
#include <math.h>

#define H 1024
#define VOCAB 50257

#define GATE_BLOCKS 1024         // 8192 virtual rows / 8 warps per block
#define LOGIT_NPB   3142         // ceil(50257 / 16)
#define PIN_ROWS    12288        // first 48MB of W_out pinned in L2
#define FIN_BLOCKS  197          // ceil(50257 / 256)

// Scratch (__device__ globals — allocation-free rule)
__device__ float g_part[8192];         // gates partials: [0,4096)=Wih, [4096,8192)=Whh
__device__ float g_h1[H], g_h1r[H], g_c1[H];
__device__ float g_h2[H];
__device__ float2 g_pairs[LOGIT_NPB];

// ---------------------------------------------------------------------------
__device__ __forceinline__ float sigmoidf_fast(float x) {
    return 1.f / (1.f + __expf(-x));
}

__device__ __forceinline__ void merge_pair(float& m, float& s, float m2, float s2) {
    if (m2 > m) { float t = s; s = s2 + t * __expf(m - m2); m = m2; }
    else if (m2 != -INFINITY) { s += s2 * __expf(m2 - m); }
}

// 256-bit loads with L2 eviction policy (sm_103a requires .v4.b64 for hints)
struct f8 { float4 a, b; };

__device__ __forceinline__ f8 ld8_evict_last(const float* p) {
    f8 v;
    asm volatile(
        "{\n\t"
        ".reg .b64 q0,q1,q2,q3;\n\t"
        "ld.global.nc.L2::evict_last.v4.b64 {q0,q1,q2,q3}, [%8];\n\t"
        "mov.b64 {%0,%1}, q0;\n\t"
        "mov.b64 {%2,%3}, q1;\n\t"
        "mov.b64 {%4,%5}, q2;\n\t"
        "mov.b64 {%6,%7}, q3;\n\t"
        "}"
        : "=f"(v.a.x), "=f"(v.a.y), "=f"(v.a.z), "=f"(v.a.w),
          "=f"(v.b.x), "=f"(v.b.y), "=f"(v.b.z), "=f"(v.b.w)
        : "l"(p));
    return v;
}

__device__ __forceinline__ f8 ld8_evict_first(const float* p) {
    f8 v;
    asm volatile(
        "{\n\t"
        ".reg .b64 q0,q1,q2,q3;\n\t"
        "ld.global.nc.L2::evict_first.v4.b64 {q0,q1,q2,q3}, [%8];\n\t"
        "mov.b64 {%0,%1}, q0;\n\t"
        "mov.b64 {%2,%3}, q1;\n\t"
        "mov.b64 {%4,%5}, q2;\n\t"
        "mov.b64 {%6,%7}, q3;\n\t"
        "}"
        : "=f"(v.a.x), "=f"(v.a.y), "=f"(v.a.z), "=f"(v.a.w),
          "=f"(v.b.x), "=f"(v.b.y), "=f"(v.b.z), "=f"(v.b.w)
        : "l"(p));
    return v;
}

__device__ __forceinline__ float dot8(const f8& w, const float4& x0, const float4& x1) {
    return w.a.x * x0.x + w.a.y * x0.y + w.a.z * x0.z + w.a.w * x0.w
         + w.b.x * x1.x + w.b.y * x1.y + w.b.z * x1.z + w.b.w * x1.w;
}

// ---------------------------------------------------------------------------
// Gates GEMV, split across Wih/Whh: 8192 virtual rows, one warp each.
// Blocks [0,512): Wih against relu(x).  Blocks [512,1024): Whh against h.
// x source: emb[id[0]] when idptr != null (layer 1), else xbase (layer 2).
// Weights loaded 256-bit with L2::evict_last (pinned across graph replays).
// ---------------------------------------------------------------------------
__global__ void __launch_bounds__(256) gates_kernel(
        const float* __restrict__ Wih, const float* __restrict__ Whh,
        const float* __restrict__ xbase, const int* __restrict__ idptr,
        const float* __restrict__ hvec) {
    __shared__ float sv[H];
    int t = threadIdx.x;
    bool isA = blockIdx.x < (GATE_BLOCKS / 2);

    if (isA) {
        const float* x = idptr ? (xbase + (long)idptr[0] * H) : xbase;
        for (int i = t; i < H; i += 256) sv[i] = fmaxf(x[i], 0.f);
    } else {
        for (int i = t; i < H; i += 256) sv[i] = hvec[i];
    }
    __syncthreads();

    int warp = t >> 5, lane = t & 31;
    int vr  = blockIdx.x * 8 + warp;          // virtual row [0, 8192)
    int row = vr & 4095;
    const float* W = (isA ? Wih : Whh) + (long)row * H;

    // 128 8-float chunks per row; each lane takes 4 (front-batched)
    f8 w[4];
#pragma unroll
    for (int k = 0; k < 4; k++) w[k] = ld8_evict_last(W + (k * 32 + lane) * 8);

    const float4* sv4 = (const float4*)sv;
    float acc = 0.f;
#pragma unroll
    for (int k = 0; k < 4; k++) {
        int c = (k * 32 + lane) * 2;
        acc += dot8(w[k], sv4[c], sv4[c + 1]);
    }
#pragma unroll
    for (int o = 16; o > 0; o >>= 1) acc += __shfl_down_sync(0xffffffffu, acc, o);
    if (lane == 0) g_part[vr] = acc;
}

// ---------------------------------------------------------------------------
// LSTM elementwise from partials. One 1024-thread block.
// ---------------------------------------------------------------------------
__global__ void act_kernel(const float* __restrict__ bih,
                           const float* __restrict__ bhh,
                           const float* __restrict__ cin,
                           float* __restrict__ hraw,
                           float* __restrict__ hrelu,
                           float* __restrict__ cout,
                           float* __restrict__ tail, int write_tail) {
    int j = threadIdx.x;               // blockDim = 1024
    float gi = g_part[j]         + g_part[4096 + j]         + bih[j]         + bhh[j];
    float gf = g_part[j + H]     + g_part[4096 + j + H]     + bih[j + H]     + bhh[j + H];
    float gg = g_part[j + 2 * H] + g_part[4096 + j + 2 * H] + bih[j + 2 * H] + bhh[j + 2 * H];
    float go = g_part[j + 3 * H] + g_part[4096 + j + 3 * H] + bih[j + 3 * H] + bhh[j + 3 * H];
    float cn = sigmoidf_fast(gf) * cin[j] + sigmoidf_fast(gi) * tanhf(gg);
    float hn = sigmoidf_fast(go) * tanhf(cn);
    hraw[j]  = hn;
    if (hrelu) hrelu[j] = fmaxf(hn, 0.f);
    cout[j]  = cn;
    if (write_tail) {
        tail[j]     = hn;
        tail[H + j] = cn;
    }
}

// ---------------------------------------------------------------------------
// Logits GEMV: 4 warps, 4 rows/warp, 256-bit weight loads.
// Rows < PIN_ROWS: evict_last (L2-pinned across replays); rest: evict_first.
// Emits per-block online (max, sumexp) pair.
// ---------------------------------------------------------------------------
__global__ void __launch_bounds__(128) logits_kernel(
        const float* __restrict__ Wout, const float* __restrict__ bout,
        float* __restrict__ out) {
    __shared__ float4 shh[H / 4];
    __shared__ float2 wpairs[4];
    int t = threadIdx.x;
    const float4* h4 = (const float4*)g_h2;
    for (int i = t; i < H / 4; i += 128) shh[i] = h4[i];
    __syncthreads();

    int warp = t >> 5, lane = t & 31;
    int row0 = blockIdx.x * 16 + warp * 4;
    bool pinned = row0 < PIN_ROWS;

    f8 w[4][4];
#pragma unroll
    for (int r = 0; r < 4; r++) {
        long row = row0 + r;
        const float* p = Wout + (row < VOCAB ? row : 0) * (long)H;
        if (pinned) {
#pragma unroll
            for (int k = 0; k < 4; k++) w[r][k] = ld8_evict_last(p + (k * 32 + lane) * 8);
        } else {
#pragma unroll
            for (int k = 0; k < 4; k++) w[r][k] = ld8_evict_first(p + (k * 32 + lane) * 8);
        }
    }

    float acc[4] = {0.f, 0.f, 0.f, 0.f};
#pragma unroll
    for (int k = 0; k < 4; k++) {
        int c = (k * 32 + lane) * 2;
        float4 x0 = shh[c], x1 = shh[c + 1];
#pragma unroll
        for (int r = 0; r < 4; r++) acc[r] += dot8(w[r][k], x0, x1);
    }
#pragma unroll
    for (int o = 16; o > 0; o >>= 1) {
#pragma unroll
        for (int r = 0; r < 4; r++)
            acc[r] += __shfl_down_sync(0xffffffffu, acc[r], o);
    }

    if (lane == 0) {
        float m = -INFINITY, s = 0.f;
#pragma unroll
        for (int r = 0; r < 4; r++) {
            int row = row0 + r;
            if (row < VOCAB) {
                float v = acc[r] + bout[row];
                out[row] = v;
                merge_pair(m, s, v, 1.0f);
            }
        }
        wpairs[warp] = make_float2(m, s);
    }
    __syncthreads();
    if (t == 0) {
        float m = wpairs[0].x, s = wpairs[0].y;
#pragma unroll
        for (int wq = 1; wq < 4; wq++) merge_pair(m, s, wpairs[wq].x, wpairs[wq].y);
        g_pairs[blockIdx.x] = make_float2(m, s);
    }
}

// ---------------------------------------------------------------------------
// finish: each block independently reduces ALL pairs (L2-resident, 25KB) to
// lse, then subtracts it from its 256-element slice. Bit-identical per block.
// ---------------------------------------------------------------------------
__global__ void __launch_bounds__(256) finish_kernel(float* __restrict__ out) {
    __shared__ float2 red[8];
    __shared__ float s_lse;
    int t = threadIdx.x, lane = t & 31, warp = t >> 5;

    float m = -INFINITY, s = 0.f;
    for (int i = t; i < LOGIT_NPB; i += 256) {
        float2 p = g_pairs[i];
        merge_pair(m, s, p.x, p.y);
    }
#pragma unroll
    for (int o = 16; o > 0; o >>= 1) {
        float m2 = __shfl_down_sync(0xffffffffu, m, o);
        float s2 = __shfl_down_sync(0xffffffffu, s, o);
        merge_pair(m, s, m2, s2);
    }
    if (lane == 0) red[warp] = make_float2(m, s);
    __syncthreads();
    if (t == 0) {
        m = red[0].x; s = red[0].y;
#pragma unroll
        for (int wq = 1; wq < 8; wq++) merge_pair(m, s, red[wq].x, red[wq].y);
        s_lse = m + logf(s);
    }
    __syncthreads();

    int i = blockIdx.x * 256 + t;
    if (i < VOCAB) out[i] -= s_lse;
}

// ---------------------------------------------------------------------------
extern "C" void kernel_launch(void* const* d_in, const int* in_sizes, int n_in,
                              void* d_out, int out_size) {
    const int*   id   = (const int*)d_in[0];
    const float* h0   = (const float*)d_in[1];
    const float* c0   = (const float*)d_in[2];
    const float* emb  = (const float*)d_in[3];
    const float* Wih  = (const float*)d_in[4];
    const float* Whh  = (const float*)d_in[5];
    const float* bih  = (const float*)d_in[6];
    const float* bhh  = (const float*)d_in[7];
    const float* Wout = (const float*)d_in[8];
    const float* bout = (const float*)d_in[9];
    float* out = (float*)d_out;

    float *gh1, *gh1r, *gc1, *gh2;
    cudaGetSymbolAddress((void**)&gh1,  g_h1);
    cudaGetSymbolAddress((void**)&gh1r, g_h1r);
    cudaGetSymbolAddress((void**)&gc1,  g_c1);
    cudaGetSymbolAddress((void**)&gh2,  g_h2);

    int write_tail = (out_size >= VOCAB + 2 * H) ? 1 : 0;

    // layer 1: x = relu(emb[id]) (fused), h = h0, c = c0
    gates_kernel<<<GATE_BLOCKS, 256>>>(Wih, Whh, emb, id, h0);
    act_kernel<<<1, 1024>>>(bih, bhh, c0, gh1, gh1r, gc1, out + VOCAB, 0);

    // layer 2: x = relu(h1), h = h1, c = c1
    gates_kernel<<<GATE_BLOCKS, 256>>>(Wih, Whh, gh1r, nullptr, gh1);
    act_kernel<<<1, 1024>>>(bih, bhh, gc1, gh2, nullptr, gc1, out + VOCAB, write_tail);

    // vocab projection (+ online softmax pairs), then per-block lse + subtract
    logits_kernel<<<LOGIT_NPB, 128>>>(Wout, bout, out);
    finish_kernel<<<FIN_BLOCKS, 256>>>(out);
}

// round 5
// speedup vs baseline: 1.4070x; 1.4070x over previous
#include <cuda_runtime.h>
#include <math.h>

#define H 1024
#define VOCAB 50257
#define NB 148                  // blocks == persistent, one per SM (<= SM count)
#define NT 1024
#define NW (NB * 32)            // 4736 warps
#define PIN_ROWS 16384          // first 64MB of W_out pinned in L2
#define FIN_CHUNK 340           // ceil(VOCAB / NB)

// Scratch (__device__ globals — allocation-free rule)
__device__ float g_partA[8192];     // layer1 partials: [0,4096)=Wih, [4096,8192)=Whh
__device__ float g_partB[8192];     // layer2 partials
__device__ float2 g_pairs[NB];
__device__ unsigned g_cnt[4];
__device__ volatile unsigned g_gen[4];

// ---------------------------------------------------------------------------
__device__ __forceinline__ float sigmoidf_fast(float x) {
    return 1.f / (1.f + __expf(-x));
}

__device__ __forceinline__ void merge_pair(float& m, float& s, float m2, float s2) {
    if (m2 > m) { float t = s; s = s2 + t * __expf(m - m2); m = m2; }
    else if (m2 != -INFINITY) { s += s2 * __expf(m2 - m); }
}

// Grid-wide spin barrier. Safe because all NB blocks are co-resident.
// gen is monotonic across graph replays; cnt self-resets. Deterministic work.
__device__ __forceinline__ void gsync(int b) {
    __syncthreads();
    if (threadIdx.x == 0) {
        __threadfence();
        unsigned cur = g_gen[b];
        unsigned pos = atomicAdd(&g_cnt[b], 1u);
        if (pos == NB - 1) {
            g_cnt[b] = 0;
            __threadfence();
            g_gen[b] = cur + 1;
        } else {
            while (g_gen[b] == cur) __nanosleep(64);
        }
        __threadfence();
    }
    __syncthreads();
}

// 256-bit loads with L2 eviction policy (sm_103a requires .v4.b64 for hints)
struct f8 { float4 a, b; };

__device__ __forceinline__ f8 ld8_evict_last(const float* p) {
    f8 v;
    asm volatile(
        "{\n\t"
        ".reg .b64 q0,q1,q2,q3;\n\t"
        "ld.global.nc.L2::evict_last.v4.b64 {q0,q1,q2,q3}, [%8];\n\t"
        "mov.b64 {%0,%1}, q0;\n\t"
        "mov.b64 {%2,%3}, q1;\n\t"
        "mov.b64 {%4,%5}, q2;\n\t"
        "mov.b64 {%6,%7}, q3;\n\t"
        "}"
        : "=f"(v.a.x), "=f"(v.a.y), "=f"(v.a.z), "=f"(v.a.w),
          "=f"(v.b.x), "=f"(v.b.y), "=f"(v.b.z), "=f"(v.b.w)
        : "l"(p));
    return v;
}

__device__ __forceinline__ f8 ld8_evict_first(const float* p) {
    f8 v;
    asm volatile(
        "{\n\t"
        ".reg .b64 q0,q1,q2,q3;\n\t"
        "ld.global.nc.L2::evict_first.v4.b64 {q0,q1,q2,q3}, [%8];\n\t"
        "mov.b64 {%0,%1}, q0;\n\t"
        "mov.b64 {%2,%3}, q1;\n\t"
        "mov.b64 {%4,%5}, q2;\n\t"
        "mov.b64 {%6,%7}, q3;\n\t"
        "}"
        : "=f"(v.a.x), "=f"(v.a.y), "=f"(v.a.z), "=f"(v.a.w),
          "=f"(v.b.x), "=f"(v.b.y), "=f"(v.b.z), "=f"(v.b.w)
        : "l"(p));
    return v;
}

__device__ __forceinline__ float dot8(const f8& w, const float4& x0, const float4& x1) {
    return w.a.x * x0.x + w.a.y * x0.y + w.a.z * x0.z + w.a.w * x0.w
         + w.b.x * x1.x + w.b.y * x1.y + w.b.z * x1.z + w.b.w * x1.w;
}

// ---------------------------------------------------------------------------
// Gates GEMV phase: 8192 virtual rows over NW warps.
// vr < 4096: Wih row vs relu'd x (sx).  vr >= 4096: Whh row vs h (sh).
// ---------------------------------------------------------------------------
__device__ __forceinline__ void gates_phase(
        const float* __restrict__ Wih, const float* __restrict__ Whh,
        const float* sx, const float* sh, float* __restrict__ part,
        int gw, int lane) {
    for (int vr = gw; vr < 8192; vr += NW) {
        const float* W = ((vr < 4096) ? Wih : Whh) + (long)(vr & 4095) * H;
        f8 w[4];
#pragma unroll
        for (int k = 0; k < 4; k++) w[k] = ld8_evict_last(W + (k * 32 + lane) * 8);
        const float4* v4 = (const float4*)((vr < 4096) ? sx : sh);
        float acc = 0.f;
#pragma unroll
        for (int k = 0; k < 4; k++) {
            int c = (k * 32 + lane) * 2;
            acc += dot8(w[k], v4[c], v4[c + 1]);
        }
#pragma unroll
        for (int o = 16; o > 0; o >>= 1) acc += __shfl_down_sync(0xffffffffu, acc, o);
        if (lane == 0) part[vr] = acc;
    }
}

// LSTM elementwise for element j (torch gate order i, f, g, o)
__device__ __forceinline__ void act_phase(
        const float* __restrict__ part,
        const float* __restrict__ bih, const float* __restrict__ bhh,
        float cin, float& hout, float& cout, int j) {
    float gi = part[j]         + part[4096 + j]         + bih[j]         + bhh[j];
    float gf = part[j + H]     + part[4096 + j + H]     + bih[j + H]     + bhh[j + H];
    float gg = part[j + 2 * H] + part[4096 + j + 2 * H] + bih[j + 2 * H] + bhh[j + 2 * H];
    float go = part[j + 3 * H] + part[4096 + j + 3 * H] + bih[j + 3 * H] + bhh[j + 3 * H];
    cout = sigmoidf_fast(gf) * cin + sigmoidf_fast(gi) * tanhf(gg);
    hout = sigmoidf_fast(go) * tanhf(cout);
}

// ---------------------------------------------------------------------------
// ONE persistent kernel: embed -> gates1 -> act1 -> gates2 -> act2 ->
// logits (+online softmax pairs) -> lse -> subtract. 3 grid barriers.
// ---------------------------------------------------------------------------
__global__ void __launch_bounds__(NT, 1) decoder_kernel(
        const int* __restrict__ id, const float* __restrict__ h0,
        const float* __restrict__ c0, const float* __restrict__ emb,
        const float* __restrict__ Wih, const float* __restrict__ Whh,
        const float* __restrict__ bih, const float* __restrict__ bhh,
        const float* __restrict__ Wout, const float* __restrict__ bout,
        float* __restrict__ out, int write_tail) {
    __shared__ float sx[H];
    __shared__ float sh[H];
    __shared__ float2 spair[32];
    __shared__ float s_lse;

    int t = threadIdx.x, lane = t & 31, warp = t >> 5;
    int gw = blockIdx.x * 32 + warp;

    // P0: stage relu(emb[id]) and h0 in smem (per block)
    sx[t] = fmaxf(emb[(long)id[0] * H + t], 0.f);
    sh[t] = h0[t];
    __syncthreads();

    // P1: layer-1 gates GEMV
    gates_phase(Wih, Whh, sx, sh, g_partA, gw, lane);
    gsync(0);

    // P2: act1 — computed redundantly per block; c1 stays in a register
    float h1, c1;
    act_phase(g_partA, bih, bhh, c0[t], h1, c1, t);
    __syncthreads();
    sx[t] = fmaxf(h1, 0.f);
    sh[t] = h1;
    __syncthreads();

    // P3: layer-2 gates GEMV (same weights per reference)
    gates_phase(Wih, Whh, sx, sh, g_partB, gw, lane);
    gsync(1);

    // P4: act2 — redundant per block; block 0 writes the (h, c) tail
    float h2, c2;
    act_phase(g_partB, bih, bhh, c1, h2, c2, t);
    __syncthreads();
    sx[t] = h2;
    if (write_tail && blockIdx.x == 0) {
        out[VOCAB + t]     = h2;
        out[VOCAB + H + t] = c2;
    }
    __syncthreads();

    // P5: logits GEMV + per-warp online (max, sumexp)
    float m = -INFINITY, s = 0.f;
    const float4* h4 = (const float4*)sx;
    for (int row = gw; row < VOCAB; row += NW) {
        const float* p = Wout + (long)row * H;
        f8 w[4];
        if (row < PIN_ROWS) {
#pragma unroll
            for (int k = 0; k < 4; k++) w[k] = ld8_evict_last(p + (k * 32 + lane) * 8);
        } else {
#pragma unroll
            for (int k = 0; k < 4; k++) w[k] = ld8_evict_first(p + (k * 32 + lane) * 8);
        }
        float acc = 0.f;
#pragma unroll
        for (int k = 0; k < 4; k++) {
            int c = (k * 32 + lane) * 2;
            acc += dot8(w[k], h4[c], h4[c + 1]);
        }
#pragma unroll
        for (int o = 16; o > 0; o >>= 1) acc += __shfl_down_sync(0xffffffffu, acc, o);
        if (lane == 0) {
            float v = acc + bout[row];
            out[row] = v;
            merge_pair(m, s, v, 1.0f);
        }
    }
    if (lane == 0) spair[warp] = make_float2(m, s);
    __syncthreads();
    if (t == 0) {
        float mm = spair[0].x, ss = spair[0].y;
#pragma unroll
        for (int wq = 1; wq < 32; wq++) merge_pair(mm, ss, spair[wq].x, spair[wq].y);
        g_pairs[blockIdx.x] = make_float2(mm, ss);
    }
    gsync(2);

    // P6: every block redundantly reduces g_pairs (identical order => identical
    // bits), then subtracts lse from its slice of out.
    {
        float mm = -INFINITY, ss = 0.f;
        if (t < NB) { float2 p = g_pairs[t]; mm = p.x; ss = p.y; }
#pragma unroll
        for (int o = 16; o > 0; o >>= 1) {
            float m2 = __shfl_down_sync(0xffffffffu, mm, o);
            float s2 = __shfl_down_sync(0xffffffffu, ss, o);
            merge_pair(mm, ss, m2, s2);
        }
        if (lane == 0) spair[warp] = make_float2(mm, ss);
        __syncthreads();
        if (t == 0) {
            mm = spair[0].x; ss = spair[0].y;
#pragma unroll
            for (int wq = 1; wq < 5; wq++) merge_pair(mm, ss, spair[wq].x, spair[wq].y);
            s_lse = mm + logf(ss);
        }
        __syncthreads();
    }
    int i = blockIdx.x * FIN_CHUNK + t;
    if (t < FIN_CHUNK && i < VOCAB) out[i] -= s_lse;
}

// ---------------------------------------------------------------------------
extern "C" void kernel_launch(void* const* d_in, const int* in_sizes, int n_in,
                              void* d_out, int out_size) {
    const int*   id   = (const int*)d_in[0];
    const float* h0   = (const float*)d_in[1];
    const float* c0   = (const float*)d_in[2];
    const float* emb  = (const float*)d_in[3];
    const float* Wih  = (const float*)d_in[4];
    const float* Whh  = (const float*)d_in[5];
    const float* bih  = (const float*)d_in[6];
    const float* bhh  = (const float*)d_in[7];
    const float* Wout = (const float*)d_in[8];
    const float* bout = (const float*)d_in[9];
    float* out = (float*)d_out;

    int write_tail = (out_size >= VOCAB + 2 * H) ? 1 : 0;

    decoder_kernel<<<NB, NT>>>(id, h0, c0, emb, Wih, Whh, bih, bhh,
                               Wout, bout, out, write_tail);
}